// round 6
// baseline (speedup 1.0000x reference)
#include <cuda_runtime.h>
#include <stdint.h>

#define GRID_N 256

// dx = fp32(20/255); R = fp32(1/dx). XLA rewrites A/dx -> A*(1/dx), constant-folded.
#define DXF (20.0f / 255.0f)
#define RF  (1.0f / DXF)

__device__ __forceinline__ void deposit(float px, float py, float pz, float w,
                                        float* __restrict__ grid)
{
    // fi = (p + 10) * R ; then fi + 0.5, trunc toward zero.
    // __fmul_rn/__fadd_rn forbid FFMA contraction (XLA emits separate mul/add).
    float fx = __fadd_rn(__fmul_rn(__fadd_rn(px, 10.0f), RF), 0.5f);
    float fy = __fadd_rn(__fmul_rn(__fadd_rn(py, 10.0f), RF), 0.5f);
    float fz = __fadd_rn(__fmul_rn(__fadd_rn(pz, 10.0f), RF), 0.5f);

    int ix = (int)fx;   // cvt.rzi: trunc toward zero == astype(int32)
    int iy = (int)fy;
    int iz = (int)fz;

    bool in_grid = (ix >= 0) & (ix < GRID_N) &
                   (iy >= 0) & (iy < GRID_N) &
                   (iz >= 0) & (iz < GRID_N);
    if (in_grid) {
        int flat = (ix * GRID_N + iy) * GRID_N + iz;
        atomicAdd(&grid[flat], w);   // no return use -> REDG, L2-resident
    }
}

__global__ void __launch_bounds__(256) scatter_kernel_v4(
    const float* __restrict__ positions,  // [N,3]
    const float* __restrict__ weights,    // [N]
    float* __restrict__ grid,
    int n_particles)
{
    int t = blockIdx.x * blockDim.x + threadIdx.x;
    int base = 4 * t;

    if (base + 3 < n_particles) {
        // Fast path: 4 particles via 3 coalesced float4 loads + 1 float4 weights.
        const float4* p4 = (const float4*)positions;
        float4 a = __ldg(&p4[3 * t + 0]);
        float4 b = __ldg(&p4[3 * t + 1]);
        float4 c = __ldg(&p4[3 * t + 2]);
        float4 w = __ldg(&((const float4*)weights)[t]);

        deposit(a.x, a.y, a.z, w.x, grid);
        deposit(a.w, b.x, b.y, w.y, grid);
        deposit(b.z, b.w, c.x, w.z, grid);
        deposit(c.y, c.z, c.w, w.w, grid);
    } else if (base < n_particles) {
        // Tail: scalar per-particle.
        for (int i = base; i < n_particles; i++) {
            float px = __ldg(&positions[3 * i + 0]);
            float py = __ldg(&positions[3 * i + 1]);
            float pz = __ldg(&positions[3 * i + 2]);
            float w  = __ldg(&weights[i]);
            deposit(px, py, pz, w, grid);
        }
    }
}

extern "C" void kernel_launch(void* const* d_in, const int* in_sizes, int n_in,
                              void* d_out, int out_size)
{
    const float* positions = (const float*)d_in[0];
    const float* weights   = (const float*)d_in[1];
    float* grid            = (float*)d_out;

    int n_particles = in_sizes[1];  // weights has N elements; positions has 3N

    cudaMemsetAsync(grid, 0, (size_t)out_size * sizeof(float), 0);

    int threads = 256;
    int n_threads_total = (n_particles + 3) / 4;
    int blocks = (n_threads_total + threads - 1) / threads;
    scatter_kernel_v4<<<blocks, threads>>>(positions, weights, grid, n_particles);
}

// round 7
// speedup vs baseline: 1.1078x; 1.1078x over previous
#include <cuda_runtime.h>
#include <stdint.h>

#define GRID_N 256

// dx = fp32(20/255); R = fp32(1/dx). XLA rewrites A/dx -> A*(1/dx), constant-folded.
#define DXF (20.0f / 255.0f)
#define RF  (1.0f / DXF)

__device__ __forceinline__ void deposit(float px, float py, float pz, float w,
                                        float* __restrict__ grid)
{
    // fi = (p + 10) * R ; then fi + 0.5, trunc toward zero.
    // __fmul_rn/__fadd_rn forbid FFMA contraction (XLA emits separate mul/add).
    float fx = __fadd_rn(__fmul_rn(__fadd_rn(px, 10.0f), RF), 0.5f);
    float fy = __fadd_rn(__fmul_rn(__fadd_rn(py, 10.0f), RF), 0.5f);
    float fz = __fadd_rn(__fmul_rn(__fadd_rn(pz, 10.0f), RF), 0.5f);

    int ix = (int)fx;   // cvt.rzi: trunc toward zero == astype(int32)
    int iy = (int)fy;
    int iz = (int)fz;

    bool in_grid = (ix >= 0) & (ix < GRID_N) &
                   (iy >= 0) & (iy < GRID_N) &
                   (iz >= 0) & (iz < GRID_N);
    if (in_grid) {
        int flat = (ix * GRID_N + iy) * GRID_N + iz;
        atomicAdd(&grid[flat], w);   // no return use -> REDG, L2-resident
    }
}

__global__ void __launch_bounds__(256) scatter_kernel_v4s(
    const float* __restrict__ positions,  // [N,3]
    const float* __restrict__ weights,    // [N]
    float* __restrict__ grid,
    int n_particles)
{
    int t = blockIdx.x * blockDim.x + threadIdx.x;
    int base = 4 * t;

    if (base + 3 < n_particles) {
        // 4 particles via 3 coalesced float4 loads + 1 float4 weights.
        // __ldcs = evict-first streaming: don't displace the grid from L2.
        const float4* p4 = (const float4*)positions;
        float4 a = __ldcs(&p4[3 * t + 0]);
        float4 b = __ldcs(&p4[3 * t + 1]);
        float4 c = __ldcs(&p4[3 * t + 2]);
        float4 w = __ldcs(&((const float4*)weights)[t]);

        deposit(a.x, a.y, a.z, w.x, grid);
        deposit(a.w, b.x, b.y, w.y, grid);
        deposit(b.z, b.w, c.x, w.z, grid);
        deposit(c.y, c.z, c.w, w.w, grid);
    } else if (base < n_particles) {
        // Tail: scalar per-particle.
        for (int i = base; i < n_particles; i++) {
            float px = __ldcs(&positions[3 * i + 0]);
            float py = __ldcs(&positions[3 * i + 1]);
            float pz = __ldcs(&positions[3 * i + 2]);
            float w  = __ldcs(&weights[i]);
            deposit(px, py, pz, w, grid);
        }
    }
}

extern "C" void kernel_launch(void* const* d_in, const int* in_sizes, int n_in,
                              void* d_out, int out_size)
{
    const float* positions = (const float*)d_in[0];
    const float* weights   = (const float*)d_in[1];
    float* grid            = (float*)d_out;

    int n_particles = in_sizes[1];  // weights has N elements; positions has 3N

    // Memset parks the zeroed grid in L2 (dirty lines); streaming loads with
    // evict-first should keep it resident for the atomics.
    cudaMemsetAsync(grid, 0, (size_t)out_size * sizeof(float), 0);

    int threads = 256;
    int n_threads_total = (n_particles + 3) / 4;
    int blocks = (n_threads_total + threads - 1) / threads;
    scatter_kernel_v4s<<<blocks, threads>>>(positions, weights, grid, n_particles);
}

// round 8
// speedup vs baseline: 1.2506x; 1.1288x over previous
#include <cuda_runtime.h>
#include <stdint.h>

#define GRID_N 256

// dx = fp32(20/255); R = fp32(1/dx). XLA rewrites A/dx -> A*(1/dx), constant-folded.
#define DXF (20.0f / 255.0f)
#define RF  (1.0f / DXF)

// Reduction with L2 evict_last policy: grid lines win capacity fights against
// the evict_first (__ldcs) particle stream.
__device__ __forceinline__ void red_add_evict_last(float* addr, float v, uint64_t policy)
{
    asm volatile("red.global.add.L2::cache_hint.f32 [%0], %1, %2;"
                 :: "l"(addr), "f"(v), "l"(policy) : "memory");
}

__device__ __forceinline__ uint64_t make_evict_last_policy()
{
    uint64_t p;
    asm("createpolicy.fractional.L2::evict_last.b64 %0, 1.0;" : "=l"(p));
    return p;
}

__device__ __forceinline__ void deposit(float px, float py, float pz, float w,
                                        float* __restrict__ grid, uint64_t policy)
{
    // fi = (p + 10) * R ; then fi + 0.5, trunc toward zero.
    // __fmul_rn/__fadd_rn forbid FFMA contraction (XLA emits separate mul/add).
    float fx = __fadd_rn(__fmul_rn(__fadd_rn(px, 10.0f), RF), 0.5f);
    float fy = __fadd_rn(__fmul_rn(__fadd_rn(py, 10.0f), RF), 0.5f);
    float fz = __fadd_rn(__fmul_rn(__fadd_rn(pz, 10.0f), RF), 0.5f);

    int ix = (int)fx;   // cvt.rzi: trunc toward zero == astype(int32)
    int iy = (int)fy;
    int iz = (int)fz;

    bool in_grid = (ix >= 0) & (ix < GRID_N) &
                   (iy >= 0) & (iy < GRID_N) &
                   (iz >= 0) & (iz < GRID_N);
    if (in_grid) {
        int flat = (ix * GRID_N + iy) * GRID_N + iz;
        red_add_evict_last(&grid[flat], w, policy);
    }
}

__global__ void __launch_bounds__(256) scatter_kernel_v4p(
    const float* __restrict__ positions,  // [N,3]
    const float* __restrict__ weights,    // [N]
    float* __restrict__ grid,
    int n_particles)
{
    int t = blockIdx.x * blockDim.x + threadIdx.x;
    int base = 4 * t;
    uint64_t policy = make_evict_last_policy();

    if (base + 3 < n_particles) {
        // 4 particles via 3 coalesced float4 loads + 1 float4 weights.
        // __ldcs = evict-first streaming: don't displace the grid from L2.
        const float4* p4 = (const float4*)positions;
        float4 a = __ldcs(&p4[3 * t + 0]);
        float4 b = __ldcs(&p4[3 * t + 1]);
        float4 c = __ldcs(&p4[3 * t + 2]);
        float4 w = __ldcs(&((const float4*)weights)[t]);

        deposit(a.x, a.y, a.z, w.x, grid, policy);
        deposit(a.w, b.x, b.y, w.y, grid, policy);
        deposit(b.z, b.w, c.x, w.z, grid, policy);
        deposit(c.y, c.z, c.w, w.w, grid, policy);
    } else if (base < n_particles) {
        // Tail: scalar per-particle.
        for (int i = base; i < n_particles; i++) {
            float px = __ldcs(&positions[3 * i + 0]);
            float py = __ldcs(&positions[3 * i + 1]);
            float pz = __ldcs(&positions[3 * i + 2]);
            float w  = __ldcs(&weights[i]);
            deposit(px, py, pz, w, grid, policy);
        }
    }
}

extern "C" void kernel_launch(void* const* d_in, const int* in_sizes, int n_in,
                              void* d_out, int out_size)
{
    const float* positions = (const float*)d_in[0];
    const float* weights   = (const float*)d_in[1];
    float* grid            = (float*)d_out;

    int n_particles = in_sizes[1];  // weights has N elements; positions has 3N

    // Memset parks the zeroed grid in L2 (dirty lines); evict_last atomics +
    // evict_first streaming loads should keep it resident.
    cudaMemsetAsync(grid, 0, (size_t)out_size * sizeof(float), 0);

    int threads = 256;
    int n_threads_total = (n_particles + 3) / 4;
    int blocks = (n_threads_total + threads - 1) / threads;
    scatter_kernel_v4p<<<blocks, threads>>>(positions, weights, grid, n_particles);
}